// round 12
// baseline (speedup 1.0000x reference)
#include <cuda_runtime.h>
#include <cuda_fp16.h>
#include <cstdint>

// ViT patch embedding, fp16 mma.sync m16n8k16 with f16 accumulators
// (flushed to f32 every 128-k) — tests whether f16-acc HMMA runs 2x f32-acc.
// GEMM: block 128x256, BK=64, warp tile 64x64, 256 thr, 1 blk/SM,
// 3-stage cp.async ring, ldmatrix.x4, canonical 128B XOR swizzle.
// Prepass: warp-per-patch patchify->fp16 + W->fp16.

#define NPATCH  196
#define NIMG    128
#define KDIM    768
#define NDIM    768
#define MTOT    25088

#define BM 128
#define BN 256
#define BK 64
#define NITER (KDIM / BK)              // 12
#define AROW_B 128                     // bytes per row (64 halves)
#define ASTAGE_B (BM * AROW_B)         // 16384
#define BSTAGE_B (BN * AROW_B)         // 32768
#define STAGE_BYTES (ASTAGE_B + BSTAGE_B)   // 49152
#define NSTG 3
#define SMEM_BYTES (NSTG * STAGE_BYTES)     // 147456

__device__ __half A_pre[(size_t)MTOT * KDIM];   // 38.5 MB
__device__ __half W_h[(size_t)NDIM * KDIM];     // 1.18 MB

// f16-accumulator MMA: D(f16x4 in 2 regs) = A*B + C
__device__ __forceinline__ void mma_f16a(uint32_t* c, const uint32_t* a, const uint32_t* b) {
    asm volatile(
        "mma.sync.aligned.m16n8k16.row.col.f16.f16.f16.f16 "
        "{%0,%1}, {%2,%3,%4,%5}, {%6,%7}, {%0,%1};\n"
        : "+r"(c[0]), "+r"(c[1])
        : "r"(a[0]), "r"(a[1]), "r"(a[2]), "r"(a[3]), "r"(b[0]), "r"(b[1]));
}
__device__ __forceinline__ void ldsm4(uint32_t* r, uint32_t addr) {
    asm volatile("ldmatrix.sync.aligned.m8n8.x4.shared.b16 {%0,%1,%2,%3}, [%4];"
                 : "=r"(r[0]), "=r"(r[1]), "=r"(r[2]), "=r"(r[3]) : "r"(addr));
}
__device__ __forceinline__ void cp16(uint32_t s, const void* g) {
    asm volatile("cp.async.cg.shared.global [%0], [%1], 16;\n" :: "r"(s), "l"(g));
}
__device__ __forceinline__ void cp_commit() { asm volatile("cp.async.commit_group;\n"); }
template <int N>
__device__ __forceinline__ void cp_wait() { asm volatile("cp.async.wait_group %0;\n" :: "n"(N)); }

// ---------------- prepass: warp-per-patch patchify->fp16; warp-per-row for W ----
#define PRE_BLOCKS ((MTOT + NDIM + 7) / 8)

__global__ __launch_bounds__(256) void prepass(const float* __restrict__ images,
                                               const float* __restrict__ W) {
    const int wg   = blockIdx.x * 8 + (threadIdx.x >> 5);
    const int lane = threadIdx.x & 31;
    if (wg < MTOT) {
        const int m   = wg;
        const int img = m / NPATCH, pch = m - img * NPATCH;
        const int Pi  = pch / 14,   Pj  = pch - Pi * 14;
        const float* src = images + (size_t)img * 150528
                         + (size_t)(Pi * 16 + (lane >> 1)) * 224 + Pj * 16 + (lane & 1) * 8;
        __half* dst = A_pre + (size_t)m * KDIM + lane * 8;
        #pragma unroll
        for (int p = 0; p < 3; ++p) {
            const float4 v0 = *reinterpret_cast<const float4*>(src + (size_t)p * 50176);
            const float4 v1 = *reinterpret_cast<const float4*>(src + (size_t)p * 50176 + 4);
            __half2 h[4];
            h[0] = __floats2half2_rn(v0.x, v0.y);
            h[1] = __floats2half2_rn(v0.z, v0.w);
            h[2] = __floats2half2_rn(v1.x, v1.y);
            h[3] = __floats2half2_rn(v1.z, v1.w);
            *reinterpret_cast<uint4*>(dst + p * 256) = *reinterpret_cast<uint4*>(h);
        }
    } else if (wg < MTOT + NDIM) {
        const int n = wg - MTOT;
        const float* src = W + (size_t)n * KDIM + lane * 8;
        __half* dst = W_h + (size_t)n * KDIM + lane * 8;
        #pragma unroll
        for (int p = 0; p < 3; ++p) {
            const float4 v0 = *reinterpret_cast<const float4*>(src + p * 256);
            const float4 v1 = *reinterpret_cast<const float4*>(src + p * 256 + 4);
            __half2 h[4];
            h[0] = __floats2half2_rn(v0.x, v0.y);
            h[1] = __floats2half2_rn(v0.z, v0.w);
            h[2] = __floats2half2_rn(v1.x, v1.y);
            h[3] = __floats2half2_rn(v1.z, v1.w);
            *reinterpret_cast<uint4*>(dst + p * 256) = *reinterpret_cast<uint4*>(h);
        }
    }
}

// ---------------- main GEMM ----------------
__global__ __launch_bounds__(256, 1) void vit_gemm(
    const float* __restrict__ bias,
    const float* __restrict__ cls,
    float* __restrict__ out)
{
    extern __shared__ __align__(16) char smc[];

    const int tid  = threadIdx.x;
    const int lane = tid & 31;
    const int warp = tid >> 5;          // 0..7
    const int wm   = warp & 1;          // 2 m-positions of 64
    const int wn   = warp >> 1;         // 4 n-positions of 64
    const int g    = lane >> 2;         // 0..7
    const int tg   = lane & 3;          // 0..3

    const int bm = blockIdx.y * BM;
    const int bn = blockIdx.x * BN;

    // ---------------- loader mapping (quarter-warp = one 128B row) ----------------
    const int lq = lane >> 3;           // 0..3 row slot
    const int lc = lane & 7;            // 0..7 chunk
    const uint32_t x_even = (uint32_t)((lc ^ lq) << 4);
    const uint32_t x_odd  = (uint32_t)((lc ^ (lq + 4)) << 4);

    const __half* asrc = A_pre + (size_t)(bm + 16 * warp + lq) * KDIM + lc * 8;
    const __half* bsrc = W_h   + (size_t)(bn + 32 * warp + lq) * KDIM + lc * 8;
    const uint32_t sts_a0 = (uint32_t)(16 * warp + lq) * AROW_B;
    const uint32_t sts_b0 = (uint32_t)ASTAGE_B + (uint32_t)(32 * warp + lq) * AROW_B;

    const uint32_t sbase = (uint32_t)__cvta_generic_to_shared(smc);

    auto load_tile = [&](int it) {
        const int st = it - (it / NSTG) * NSTG;
        const int k0 = it * BK;
        const uint32_t sb0 = sbase + (uint32_t)st * STAGE_BYTES;
        #pragma unroll
        for (int i = 0; i < 4; ++i)
            cp16(sb0 + sts_a0 + i * 512u + ((i & 1) ? x_odd : x_even),
                 asrc + (size_t)i * (4 * KDIM) + k0);
        #pragma unroll
        for (int i = 0; i < 8; ++i)
            cp16(sb0 + sts_b0 + i * 512u + ((i & 1) ? x_odd : x_even),
                 bsrc + (size_t)i * (4 * KDIM) + k0);
    };

    float acc[4][8][4];                 // f32 masters
    #pragma unroll
    for (int mt = 0; mt < 4; ++mt)
        #pragma unroll
        for (int nt = 0; nt < 8; ++nt)
            #pragma unroll
            for (int r = 0; r < 4; ++r) acc[mt][nt][r] = 0.f;

    uint32_t acch[4][8][2];             // f16 chunk accumulators
    #pragma unroll
    for (int mt = 0; mt < 4; ++mt)
        #pragma unroll
        for (int nt = 0; nt < 8; ++nt)
            acch[mt][nt][0] = acch[mt][nt][1] = 0u;

    load_tile(0); cp_commit();
    load_tile(1); cp_commit();

    // ---------------- ldmatrix lane constants ----------------
    const int a_sub = (lane & 7) + ((lane >> 3) & 1) * 8;
    const int chA   = (lane >> 4) & 1;
    const int b_sub = (lane & 7) + ((lane >> 4) & 1) * 8;
    const int chB   = (lane >> 3) & 1;
    const uint32_t lx = (uint32_t)(lane & 7);
    const uint32_t aBase = (uint32_t)(wm * 64 + a_sub) * AROW_B;
    const uint32_t bBase = (uint32_t)ASTAGE_B + (uint32_t)(wn * 64 + b_sub) * AROW_B;

    for (int it = 0; it < NITER; ++it) {
        if (it == NITER - 1) cp_wait<0>(); else cp_wait<1>();
        __syncthreads();

        const int st = it - (it / NSTG) * NSTG;
        const uint32_t stg = sbase + (uint32_t)st * STAGE_BYTES;

        #pragma unroll
        for (int ks = 0; ks < 4; ++ks) {
            uint32_t af[4][4], bf[4][4];
            const uint32_t ach = ((uint32_t)(2 * ks + chA) ^ lx) << 4;
            const uint32_t bch = ((uint32_t)(2 * ks + chB) ^ lx) << 4;
            #pragma unroll
            for (int mt = 0; mt < 4; ++mt)
                ldsm4(af[mt], stg + aBase + mt * 2048u + ach);
            #pragma unroll
            for (int p = 0; p < 4; ++p)
                ldsm4(bf[p], stg + bBase + p * 2048u + bch);

            if (ks == 0 && it + 2 < NITER) { load_tile(it + 2); cp_commit(); }

            #pragma unroll
            for (int mt = 0; mt < 4; ++mt)
                #pragma unroll
                for (int nt = 0; nt < 8; ++nt)
                    mma_f16a(acch[mt][nt], af[mt], &bf[nt >> 1][(nt & 1) * 2]);
        }

        // flush f16 chunk accumulators to f32 masters every 2 iters (128-k)
        if (it & 1) {
            #pragma unroll
            for (int mt = 0; mt < 4; ++mt)
                #pragma unroll
                for (int nt = 0; nt < 8; ++nt) {
                    const float2 lo = __half22float2(
                        *reinterpret_cast<const __half2*>(&acch[mt][nt][0]));
                    const float2 hi = __half22float2(
                        *reinterpret_cast<const __half2*>(&acch[mt][nt][1]));
                    acc[mt][nt][0] += lo.x;
                    acc[mt][nt][1] += lo.y;
                    acc[mt][nt][2] += hi.x;
                    acc[mt][nt][3] += hi.y;
                    acch[mt][nt][0] = 0u;
                    acch[mt][nt][1] = 0u;
                }
        }
    }

    // ---------------- epilogue: bias + scatter ----------------
    float bv[8][2];
    #pragma unroll
    for (int nt = 0; nt < 8; ++nt) {
        const int col = bn + wn * 64 + nt * 8 + tg * 2;
        bv[nt][0] = bias[col];
        bv[nt][1] = bias[col + 1];
    }

    #pragma unroll
    for (int mt = 0; mt < 4; ++mt) {
        #pragma unroll
        for (int rh = 0; rh < 2; ++rh) {
            const int m     = bm + wm * 64 + mt * 16 + rh * 8 + g;
            const int img   = m / NPATCH;
            const int patch = m - img * NPATCH;
            float* orow = out + ((size_t)img * 197 + patch + 1) * NDIM;
            #pragma unroll
            for (int nt = 0; nt < 8; ++nt) {
                const int col = bn + wn * 64 + nt * 8 + tg * 2;
                float2 v;
                v.x = acc[mt][nt][rh * 2 + 0] + bv[nt][0];
                v.y = acc[mt][nt][rh * 2 + 1] + bv[nt][1];
                *reinterpret_cast<float2*>(orow + col) = v;
            }
        }
    }

    // ---------------- fused CLS rows ----------------
    if (blockIdx.y == 0) {
        const int gid = blockIdx.x * 256 + tid;            // 0..767
        const float4* c4 = (const float4*)cls;
        for (int i = gid; i < NIMG * (NDIM / 4); i += 768) {
            const int img = i / (NDIM / 4);
            const int n4  = i - img * (NDIM / 4);
            reinterpret_cast<float4*>(out + (size_t)img * 197 * NDIM)[n4] = c4[n4];
        }
    }
}

extern "C" void kernel_launch(void* const* d_in, const int* in_sizes, int n_in,
                              void* d_out, int out_size) {
    const float* images = (const float*)d_in[0];
    const float* W      = (const float*)d_in[1];
    const float* b      = (const float*)d_in[2];
    const float* cls    = (const float*)d_in[3];
    float* out          = (float*)d_out;

    cudaFuncSetAttribute(vit_gemm, cudaFuncAttributeMaxDynamicSharedMemorySize, SMEM_BYTES);

    prepass<<<PRE_BLOCKS, 256>>>(images, W);
    dim3 grid(NDIM / BN, MTOT / BM);   // (3, 196), n fastest for A L2 reuse
    vit_gemm<<<grid, 256, SMEM_BYTES>>>(b, cls, out);
}

// round 13
// speedup vs baseline: 1.0152x; 1.0152x over previous
#include <cuda_runtime.h>
#include <cuda_fp16.h>
#include <cstdint>

// ViT patch embedding, fp16 mma.sync m16n8k16 (f32 acc).
// R12: patchify+f16 conversion FUSED into the GEMM A-loader
// (LDG f32 -> cvt -> swizzled STS, pipelined 2 iters ahead); prepass is W-only.
// GEMM: block 128x256, BK=64, warp tile 64x64, 256 thr, 1 blk/SM,
// 3-stage ring (B via cp.async), ldmatrix.x4, canonical 128B XOR swizzle.

#define NPATCH  196
#define NIMG    128
#define KDIM    768
#define NDIM    768
#define MTOT    25088

#define BM 128
#define BN 256
#define BK 64
#define NITER (KDIM / BK)              // 12
#define AROW_B 128                     // bytes per row (64 halves)
#define ASTAGE_B (BM * AROW_B)         // 16384
#define BSTAGE_B (BN * AROW_B)         // 32768
#define STAGE_BYTES (ASTAGE_B + BSTAGE_B)   // 49152
#define NSTG 3
#define SMEM_BYTES (NSTG * STAGE_BYTES)     // 147456

__device__ __half W_h[(size_t)NDIM * KDIM];     // 1.18 MB

__device__ __forceinline__ void mma_f16(float* c, const uint32_t* a, const uint32_t* b) {
    asm volatile(
        "mma.sync.aligned.m16n8k16.row.col.f32.f16.f16.f32 "
        "{%0,%1,%2,%3}, {%4,%5,%6,%7}, {%8,%9}, {%0,%1,%2,%3};\n"
        : "+f"(c[0]), "+f"(c[1]), "+f"(c[2]), "+f"(c[3])
        : "r"(a[0]), "r"(a[1]), "r"(a[2]), "r"(a[3]), "r"(b[0]), "r"(b[1]));
}
__device__ __forceinline__ void ldsm4(uint32_t* r, uint32_t addr) {
    asm volatile("ldmatrix.sync.aligned.m8n8.x4.shared.b16 {%0,%1,%2,%3}, [%4];"
                 : "=r"(r[0]), "=r"(r[1]), "=r"(r[2]), "=r"(r[3]) : "r"(addr));
}
__device__ __forceinline__ void cp16(uint32_t s, const void* g) {
    asm volatile("cp.async.cg.shared.global [%0], [%1], 16;\n" :: "r"(s), "l"(g));
}
__device__ __forceinline__ void cp_commit() { asm volatile("cp.async.commit_group;\n"); }
template <int N>
__device__ __forceinline__ void cp_wait() { asm volatile("cp.async.wait_group %0;\n" :: "n"(N)); }

// ---------------- prepass: W -> fp16 (warp per row) ----------------
#define WPRE_BLOCKS (NDIM / 8)          // 96 blocks x 8 warps

__global__ __launch_bounds__(256) void prepass_w(const float* __restrict__ W) {
    const int n    = blockIdx.x * 8 + (threadIdx.x >> 5);
    const int lane = threadIdx.x & 31;
    const float* src = W + (size_t)n * KDIM + lane * 8;
    __half* dst = W_h + (size_t)n * KDIM + lane * 8;
    #pragma unroll
    for (int p = 0; p < 3; ++p) {
        const float4 v0 = *reinterpret_cast<const float4*>(src + p * 256);
        const float4 v1 = *reinterpret_cast<const float4*>(src + p * 256 + 4);
        __half2 h[4];
        h[0] = __floats2half2_rn(v0.x, v0.y);
        h[1] = __floats2half2_rn(v0.z, v0.w);
        h[2] = __floats2half2_rn(v1.x, v1.y);
        h[3] = __floats2half2_rn(v1.z, v1.w);
        *reinterpret_cast<uint4*>(dst + p * 256) = *reinterpret_cast<uint4*>(h);
    }
}

// ---------------- main GEMM ----------------
__global__ __launch_bounds__(256, 1) void vit_gemm(
    const float* __restrict__ images,
    const float* __restrict__ bias,
    const float* __restrict__ cls,
    float* __restrict__ out)
{
    extern __shared__ __align__(16) char smc[];

    const int tid  = threadIdx.x;
    const int lane = tid & 31;
    const int warp = tid >> 5;          // 0..7
    const int wm   = warp & 1;          // 2 m-positions of 64
    const int wn   = warp >> 1;         // 4 n-positions of 64
    const int g    = lane >> 2;         // 0..7
    const int tg   = lane & 3;          // 0..3

    const int bm = blockIdx.y * BM;
    const int bn = blockIdx.x * BN;

    // ---------------- B loader (cp.async, quarter-warp = one 128B row) ----------
    const int lq = lane >> 3;           // 0..3 row slot
    const int lc = lane & 7;            // 0..7 chunk
    const uint32_t x_even = (uint32_t)((lc ^ lq) << 4);
    const uint32_t x_odd  = (uint32_t)((lc ^ (lq + 4)) << 4);

    const __half* bsrc = W_h + (size_t)(bn + 32 * warp + lq) * KDIM + lc * 8;
    const uint32_t sts_b0 = (uint32_t)ASTAGE_B + (uint32_t)(32 * warp + lq) * AROW_B;

    const uint32_t sbase = (uint32_t)__cvta_generic_to_shared(smc);

    auto loadB = [&](int it) {
        const int st = it - (it / NSTG) * NSTG;
        const int k0 = it * BK;
        const uint32_t sb0 = sbase + (uint32_t)st * STAGE_BYTES;
        #pragma unroll
        for (int i = 0; i < 8; ++i)
            cp16(sb0 + sts_b0 + i * 512u + ((i & 1) ? x_odd : x_even),
                 bsrc + (size_t)i * (4 * KDIM) + k0);
    };

    // ---------------- A converter (LDG f32 -> cvt -> swizzled STS) --------------
    // thread: row ar = tid&127, half ah = tid>>7 (k-range 32*ah..32*ah+31)
    // chunk j (0/1) = one image row of 16 px -> smem units 4ah+2j, 4ah+2j+1.
    const int ar = tid & 127;
    const int ah = tid >> 7;
    const int m0   = bm + ar;
    const int img0 = m0 / NPATCH;
    const int pch0 = m0 - img0 * NPATCH;
    const int Pi0  = pch0 / 14;
    const int Pj0  = pch0 - Pi0 * 14;
    const float* abase = images + (size_t)img0 * 150528 + (size_t)(Pi0 * 16) * 224 + Pj0 * 16;
    uint32_t su[4];
    #pragma unroll
    for (int z = 0; z < 4; ++z)
        su[z] = (uint32_t)(((4 * ah + z) ^ (ar & 7)) << 4);
    const uint32_t arow = (uint32_t)ar * AROW_B;

    float4 stage_v[4];   // staging for one 16-float chunk

    auto ldA = [&](int it, int j) {
        const float* src = abase + (size_t)(it >> 2) * 50176
                         + (size_t)((it & 3) * 4 + 2 * ah + j) * 224;
        const float4* s4 = reinterpret_cast<const float4*>(src);
        stage_v[0] = s4[0]; stage_v[1] = s4[1]; stage_v[2] = s4[2]; stage_v[3] = s4[3];
    };
    auto stA = [&](int it, int j) {
        const int st = it - (it / NSTG) * NSTG;
        __half2 h[8];
        h[0] = __floats2half2_rn(stage_v[0].x, stage_v[0].y);
        h[1] = __floats2half2_rn(stage_v[0].z, stage_v[0].w);
        h[2] = __floats2half2_rn(stage_v[1].x, stage_v[1].y);
        h[3] = __floats2half2_rn(stage_v[1].z, stage_v[1].w);
        h[4] = __floats2half2_rn(stage_v[2].x, stage_v[2].y);
        h[5] = __floats2half2_rn(stage_v[2].z, stage_v[2].w);
        h[6] = __floats2half2_rn(stage_v[3].x, stage_v[3].y);
        h[7] = __floats2half2_rn(stage_v[3].z, stage_v[3].w);
        char* dst = smc + (size_t)st * STAGE_BYTES + arow;
        *reinterpret_cast<uint4*>(dst + su[2 * j])     = *reinterpret_cast<uint4*>(&h[0]);
        *reinterpret_cast<uint4*>(dst + su[2 * j + 1]) = *reinterpret_cast<uint4*>(&h[4]);
    };

    float acc[4][8][4];
    #pragma unroll
    for (int mt = 0; mt < 4; ++mt)
        #pragma unroll
        for (int nt = 0; nt < 8; ++nt)
            #pragma unroll
            for (int r = 0; r < 4; ++r) acc[mt][nt][r] = 0.f;

    // prologue: stages 0 and 1
    loadB(0); cp_commit();
    loadB(1); cp_commit();
    ldA(0, 0); stA(0, 0); ldA(0, 1); stA(0, 1);
    ldA(1, 0); stA(1, 0); ldA(1, 1); stA(1, 1);

    // ---------------- ldmatrix lane constants ----------------
    const int a_sub = (lane & 7) + ((lane >> 3) & 1) * 8;
    const int chA   = (lane >> 4) & 1;
    const int b_sub = (lane & 7) + ((lane >> 4) & 1) * 8;
    const int chB   = (lane >> 3) & 1;
    const uint32_t lx = (uint32_t)(lane & 7);
    const uint32_t aBase = (uint32_t)(wm * 64 + a_sub) * AROW_B;
    const uint32_t bBase = (uint32_t)ASTAGE_B + (uint32_t)(wn * 64 + b_sub) * AROW_B;

    for (int it = 0; it < NITER; ++it) {
        if (it == NITER - 1) cp_wait<0>(); else cp_wait<1>();
        __syncthreads();

        const int st = it - (it / NSTG) * NSTG;
        const uint32_t stg = sbase + (uint32_t)st * STAGE_BYTES;
        const bool pf = (it + 2 < NITER);

        if (pf) ldA(it + 2, 0);                         // chunk0 LDG (stage it+2)

        #pragma unroll
        for (int ks = 0; ks < 4; ++ks) {
            uint32_t af[4][4], bf[4][4];
            const uint32_t ach = ((uint32_t)(2 * ks + chA) ^ lx) << 4;
            const uint32_t bch = ((uint32_t)(2 * ks + chB) ^ lx) << 4;
            #pragma unroll
            for (int mt = 0; mt < 4; ++mt)
                ldsm4(af[mt], stg + aBase + mt * 2048u + ach);
            #pragma unroll
            for (int p = 0; p < 4; ++p)
                ldsm4(bf[p], stg + bBase + p * 2048u + bch);

            if (ks == 0 && pf) { loadB(it + 2); cp_commit(); }

            #pragma unroll
            for (int mt = 0; mt < 4; ++mt)
                #pragma unroll
                for (int nt = 0; nt < 8; ++nt)
                    mma_f16(acc[mt][nt], af[mt], &bf[nt >> 1][(nt & 1) * 2]);

            if (pf) {
                if (ks == 0) { stA(it + 2, 0); }        // cvt+STS chunk0
                else if (ks == 1) { ldA(it + 2, 1); }   // chunk1 LDG
                else if (ks == 2) { stA(it + 2, 1); }   // cvt+STS chunk1
            }
        }
    }

    // ---------------- epilogue: bias + scatter ----------------
    float bv[8][2];
    #pragma unroll
    for (int nt = 0; nt < 8; ++nt) {
        const int col = bn + wn * 64 + nt * 8 + tg * 2;
        bv[nt][0] = bias[col];
        bv[nt][1] = bias[col + 1];
    }

    #pragma unroll
    for (int mt = 0; mt < 4; ++mt) {
        #pragma unroll
        for (int rh = 0; rh < 2; ++rh) {
            const int m     = bm + wm * 64 + mt * 16 + rh * 8 + g;
            const int img   = m / NPATCH;
            const int patch = m - img * NPATCH;
            float* orow = out + ((size_t)img * 197 + patch + 1) * NDIM;
            #pragma unroll
            for (int nt = 0; nt < 8; ++nt) {
                const int col = bn + wn * 64 + nt * 8 + tg * 2;
                float2 v;
                v.x = acc[mt][nt][rh * 2 + 0] + bv[nt][0];
                v.y = acc[mt][nt][rh * 2 + 1] + bv[nt][1];
                *reinterpret_cast<float2*>(orow + col) = v;
            }
        }
    }

    // ---------------- fused CLS rows ----------------
    if (blockIdx.y == 0) {
        const int gid = blockIdx.x * 256 + tid;            // 0..767
        const float4* c4 = (const float4*)cls;
        for (int i = gid; i < NIMG * (NDIM / 4); i += 768) {
            const int img = i / (NDIM / 4);
            const int n4  = i - img * (NDIM / 4);
            reinterpret_cast<float4*>(out + (size_t)img * 197 * NDIM)[n4] = c4[n4];
        }
    }
}

extern "C" void kernel_launch(void* const* d_in, const int* in_sizes, int n_in,
                              void* d_out, int out_size) {
    const float* images = (const float*)d_in[0];
    const float* W      = (const float*)d_in[1];
    const float* b      = (const float*)d_in[2];
    const float* cls    = (const float*)d_in[3];
    float* out          = (float*)d_out;

    cudaFuncSetAttribute(vit_gemm, cudaFuncAttributeMaxDynamicSharedMemorySize, SMEM_BYTES);

    prepass_w<<<WPRE_BLOCKS, 256>>>(W);
    dim3 grid(NDIM / BN, MTOT / BM);   // (3, 196), n fastest so the 3 A-sharers are concurrent
    vit_gemm<<<grid, 256, SMEM_BYTES>>>(images, b, cls, out);
}

// round 14
// speedup vs baseline: 1.0195x; 1.0042x over previous
#include <cuda_runtime.h>
#include <cuda_fp16.h>
#include <cstdint>

// ViT patch embedding, fp16 mma.sync m16n8k16 (f32 acc).
// R12: patchify+f16 conversion FUSED into the GEMM A-loader
// (LDG f32 -> cvt -> swizzled STS, pipelined 2 iters ahead); prepass is W-only.
// GEMM: block 128x256, BK=64, warp tile 64x64, 256 thr, 1 blk/SM,
// 3-stage ring (B via cp.async), ldmatrix.x4, canonical 128B XOR swizzle.

#define NPATCH  196
#define NIMG    128
#define KDIM    768
#define NDIM    768
#define MTOT    25088

#define BM 128
#define BN 256
#define BK 64
#define NITER (KDIM / BK)              // 12
#define AROW_B 128                     // bytes per row (64 halves)
#define ASTAGE_B (BM * AROW_B)         // 16384
#define BSTAGE_B (BN * AROW_B)         // 32768
#define STAGE_BYTES (ASTAGE_B + BSTAGE_B)   // 49152
#define NSTG 3
#define SMEM_BYTES (NSTG * STAGE_BYTES)     // 147456

__device__ __half W_h[(size_t)NDIM * KDIM];     // 1.18 MB

__device__ __forceinline__ void mma_f16(float* c, const uint32_t* a, const uint32_t* b) {
    asm volatile(
        "mma.sync.aligned.m16n8k16.row.col.f32.f16.f16.f32 "
        "{%0,%1,%2,%3}, {%4,%5,%6,%7}, {%8,%9}, {%0,%1,%2,%3};\n"
        : "+f"(c[0]), "+f"(c[1]), "+f"(c[2]), "+f"(c[3])
        : "r"(a[0]), "r"(a[1]), "r"(a[2]), "r"(a[3]), "r"(b[0]), "r"(b[1]));
}
__device__ __forceinline__ void ldsm4(uint32_t* r, uint32_t addr) {
    asm volatile("ldmatrix.sync.aligned.m8n8.x4.shared.b16 {%0,%1,%2,%3}, [%4];"
                 : "=r"(r[0]), "=r"(r[1]), "=r"(r[2]), "=r"(r[3]) : "r"(addr));
}
__device__ __forceinline__ void cp16(uint32_t s, const void* g) {
    asm volatile("cp.async.cg.shared.global [%0], [%1], 16;\n" :: "r"(s), "l"(g));
}
__device__ __forceinline__ void cp_commit() { asm volatile("cp.async.commit_group;\n"); }
template <int N>
__device__ __forceinline__ void cp_wait() { asm volatile("cp.async.wait_group %0;\n" :: "n"(N)); }

// ---------------- prepass: W -> fp16 (warp per row) ----------------
#define WPRE_BLOCKS (NDIM / 8)          // 96 blocks x 8 warps

__global__ __launch_bounds__(256) void prepass_w(const float* __restrict__ W) {
    const int n    = blockIdx.x * 8 + (threadIdx.x >> 5);
    const int lane = threadIdx.x & 31;
    const float* src = W + (size_t)n * KDIM + lane * 8;
    __half* dst = W_h + (size_t)n * KDIM + lane * 8;
    #pragma unroll
    for (int p = 0; p < 3; ++p) {
        const float4 v0 = *reinterpret_cast<const float4*>(src + p * 256);
        const float4 v1 = *reinterpret_cast<const float4*>(src + p * 256 + 4);
        __half2 h[4];
        h[0] = __floats2half2_rn(v0.x, v0.y);
        h[1] = __floats2half2_rn(v0.z, v0.w);
        h[2] = __floats2half2_rn(v1.x, v1.y);
        h[3] = __floats2half2_rn(v1.z, v1.w);
        *reinterpret_cast<uint4*>(dst + p * 256) = *reinterpret_cast<uint4*>(h);
    }
}

// ---------------- main GEMM ----------------
__global__ __launch_bounds__(256, 1) void vit_gemm(
    const float* __restrict__ images,
    const float* __restrict__ bias,
    const float* __restrict__ cls,
    float* __restrict__ out)
{
    extern __shared__ __align__(16) char smc[];

    const int tid  = threadIdx.x;
    const int lane = tid & 31;
    const int warp = tid >> 5;          // 0..7
    const int wm   = warp & 1;          // 2 m-positions of 64
    const int wn   = warp >> 1;         // 4 n-positions of 64
    const int g    = lane >> 2;         // 0..7
    const int tg   = lane & 3;          // 0..3

    const int bm = blockIdx.y * BM;
    const int bn = blockIdx.x * BN;

    // ---------------- B loader (cp.async, quarter-warp = one 128B row) ----------
    const int lq = lane >> 3;           // 0..3 row slot
    const int lc = lane & 7;            // 0..7 chunk
    const uint32_t x_even = (uint32_t)((lc ^ lq) << 4);
    const uint32_t x_odd  = (uint32_t)((lc ^ (lq + 4)) << 4);

    const __half* bsrc = W_h + (size_t)(bn + 32 * warp + lq) * KDIM + lc * 8;
    const uint32_t sts_b0 = (uint32_t)ASTAGE_B + (uint32_t)(32 * warp + lq) * AROW_B;

    const uint32_t sbase = (uint32_t)__cvta_generic_to_shared(smc);

    auto loadB = [&](int it) {
        const int st = it - (it / NSTG) * NSTG;
        const int k0 = it * BK;
        const uint32_t sb0 = sbase + (uint32_t)st * STAGE_BYTES;
        #pragma unroll
        for (int i = 0; i < 8; ++i)
            cp16(sb0 + sts_b0 + i * 512u + ((i & 1) ? x_odd : x_even),
                 bsrc + (size_t)i * (4 * KDIM) + k0);
    };

    // ---------------- A converter (LDG f32 -> cvt -> swizzled STS) --------------
    // thread: row ar = tid&127, half ah = tid>>7 (k-range 32*ah..32*ah+31)
    // chunk j (0/1) = one image row of 16 px -> smem units 4ah+2j, 4ah+2j+1.
    const int ar = tid & 127;
    const int ah = tid >> 7;
    const int m0   = bm + ar;
    const int img0 = m0 / NPATCH;
    const int pch0 = m0 - img0 * NPATCH;
    const int Pi0  = pch0 / 14;
    const int Pj0  = pch0 - Pi0 * 14;
    const float* abase = images + (size_t)img0 * 150528 + (size_t)(Pi0 * 16) * 224 + Pj0 * 16;
    uint32_t su[4];
    #pragma unroll
    for (int z = 0; z < 4; ++z)
        su[z] = (uint32_t)(((4 * ah + z) ^ (ar & 7)) << 4);
    const uint32_t arow = (uint32_t)ar * AROW_B;

    float4 stage_v[4];   // staging for one 16-float chunk

    auto ldA = [&](int it, int j) {
        const float* src = abase + (size_t)(it >> 2) * 50176
                         + (size_t)((it & 3) * 4 + 2 * ah + j) * 224;
        const float4* s4 = reinterpret_cast<const float4*>(src);
        stage_v[0] = s4[0]; stage_v[1] = s4[1]; stage_v[2] = s4[2]; stage_v[3] = s4[3];
    };
    auto stA = [&](int it, int j) {
        const int st = it - (it / NSTG) * NSTG;
        __half2 h[8];
        h[0] = __floats2half2_rn(stage_v[0].x, stage_v[0].y);
        h[1] = __floats2half2_rn(stage_v[0].z, stage_v[0].w);
        h[2] = __floats2half2_rn(stage_v[1].x, stage_v[1].y);
        h[3] = __floats2half2_rn(stage_v[1].z, stage_v[1].w);
        h[4] = __floats2half2_rn(stage_v[2].x, stage_v[2].y);
        h[5] = __floats2half2_rn(stage_v[2].z, stage_v[2].w);
        h[6] = __floats2half2_rn(stage_v[3].x, stage_v[3].y);
        h[7] = __floats2half2_rn(stage_v[3].z, stage_v[3].w);
        char* dst = smc + (size_t)st * STAGE_BYTES + arow;
        *reinterpret_cast<uint4*>(dst + su[2 * j])     = *reinterpret_cast<uint4*>(&h[0]);
        *reinterpret_cast<uint4*>(dst + su[2 * j + 1]) = *reinterpret_cast<uint4*>(&h[4]);
    };

    float acc[4][8][4];
    #pragma unroll
    for (int mt = 0; mt < 4; ++mt)
        #pragma unroll
        for (int nt = 0; nt < 8; ++nt)
            #pragma unroll
            for (int r = 0; r < 4; ++r) acc[mt][nt][r] = 0.f;

    // prologue: stages 0 and 1
    loadB(0); cp_commit();
    loadB(1); cp_commit();
    ldA(0, 0); stA(0, 0); ldA(0, 1); stA(0, 1);
    ldA(1, 0); stA(1, 0); ldA(1, 1); stA(1, 1);

    // ---------------- ldmatrix lane constants ----------------
    const int a_sub = (lane & 7) + ((lane >> 3) & 1) * 8;
    const int chA   = (lane >> 4) & 1;
    const int b_sub = (lane & 7) + ((lane >> 4) & 1) * 8;
    const int chB   = (lane >> 3) & 1;
    const uint32_t lx = (uint32_t)(lane & 7);
    const uint32_t aBase = (uint32_t)(wm * 64 + a_sub) * AROW_B;
    const uint32_t bBase = (uint32_t)ASTAGE_B + (uint32_t)(wn * 64 + b_sub) * AROW_B;

    for (int it = 0; it < NITER; ++it) {
        if (it == NITER - 1) cp_wait<0>(); else cp_wait<1>();
        __syncthreads();

        const int st = it - (it / NSTG) * NSTG;
        const uint32_t stg = sbase + (uint32_t)st * STAGE_BYTES;
        const bool pf = (it + 2 < NITER);

        if (pf) ldA(it + 2, 0);                         // chunk0 LDG (stage it+2)

        #pragma unroll
        for (int ks = 0; ks < 4; ++ks) {
            uint32_t af[4][4], bf[4][4];
            const uint32_t ach = ((uint32_t)(2 * ks + chA) ^ lx) << 4;
            const uint32_t bch = ((uint32_t)(2 * ks + chB) ^ lx) << 4;
            #pragma unroll
            for (int mt = 0; mt < 4; ++mt)
                ldsm4(af[mt], stg + aBase + mt * 2048u + ach);
            #pragma unroll
            for (int p = 0; p < 4; ++p)
                ldsm4(bf[p], stg + bBase + p * 2048u + bch);

            if (ks == 0 && pf) { loadB(it + 2); cp_commit(); }

            #pragma unroll
            for (int mt = 0; mt < 4; ++mt)
                #pragma unroll
                for (int nt = 0; nt < 8; ++nt)
                    mma_f16(acc[mt][nt], af[mt], &bf[nt >> 1][(nt & 1) * 2]);

            if (pf) {
                if (ks == 0) { stA(it + 2, 0); }        // cvt+STS chunk0
                else if (ks == 1) { ldA(it + 2, 1); }   // chunk1 LDG
                else if (ks == 2) { stA(it + 2, 1); }   // cvt+STS chunk1
            }
        }
    }

    // ---------------- epilogue: bias + scatter ----------------
    float bv[8][2];
    #pragma unroll
    for (int nt = 0; nt < 8; ++nt) {
        const int col = bn + wn * 64 + nt * 8 + tg * 2;
        bv[nt][0] = bias[col];
        bv[nt][1] = bias[col + 1];
    }

    #pragma unroll
    for (int mt = 0; mt < 4; ++mt) {
        #pragma unroll
        for (int rh = 0; rh < 2; ++rh) {
            const int m     = bm + wm * 64 + mt * 16 + rh * 8 + g;
            const int img   = m / NPATCH;
            const int patch = m - img * NPATCH;
            float* orow = out + ((size_t)img * 197 + patch + 1) * NDIM;
            #pragma unroll
            for (int nt = 0; nt < 8; ++nt) {
                const int col = bn + wn * 64 + nt * 8 + tg * 2;
                float2 v;
                v.x = acc[mt][nt][rh * 2 + 0] + bv[nt][0];
                v.y = acc[mt][nt][rh * 2 + 1] + bv[nt][1];
                *reinterpret_cast<float2*>(orow + col) = v;
            }
        }
    }

    // ---------------- fused CLS rows ----------------
    if (blockIdx.y == 0) {
        const int gid = blockIdx.x * 256 + tid;            // 0..767
        const float4* c4 = (const float4*)cls;
        for (int i = gid; i < NIMG * (NDIM / 4); i += 768) {
            const int img = i / (NDIM / 4);
            const int n4  = i - img * (NDIM / 4);
            reinterpret_cast<float4*>(out + (size_t)img * 197 * NDIM)[n4] = c4[n4];
        }
    }
}

extern "C" void kernel_launch(void* const* d_in, const int* in_sizes, int n_in,
                              void* d_out, int out_size) {
    const float* images = (const float*)d_in[0];
    const float* W      = (const float*)d_in[1];
    const float* b      = (const float*)d_in[2];
    const float* cls    = (const float*)d_in[3];
    float* out          = (float*)d_out;

    cudaFuncSetAttribute(vit_gemm, cudaFuncAttributeMaxDynamicSharedMemorySize, SMEM_BYTES);

    prepass_w<<<WPRE_BLOCKS, 256>>>(W);
    dim3 grid(NDIM / BN, MTOT / BM);   // (3, 196), n fastest so the 3 A-sharers are concurrent
    vit_gemm<<<grid, 256, SMEM_BYTES>>>(images, b, cls, out);
}